// round 7
// baseline (speedup 1.0000x reference)
#include <cuda_runtime.h>
#include <cuda_bf16.h>
#include <cstdint>
#include <cstddef>

// ============================================================================
// HQQSVDLinear forward_int8 on GB300 (sm_103 base ISA — no tcgen05 through
// this toolchain; verified round 6). Exact int8 IMMA path:
//   out[n,o] = (x_q[n,:] . W_q[o,:]) * sx[n] * sw[o] + bias[o]
// Phases:
//   k_quant_x : per-token dynamic int8 quant of x  -> g_Xq (int8), g_sx
//   k_corr    : corr = svd_up @ svd_down           -> g_corr (fp32)
//   k_quant_w : W = (q-zp)*scale + corr ; row max  -> g_sw ; quant -> g_Wq
//   k_gemm    : mma.sync m16n8k32 s8 GEMM, CTA 128x128, BK=64, 4-stage
//               cp.async pipeline, ldmatrix fragments, fused epilogue
// ============================================================================

#define NTOK 4096
#define ODIM 4096
#define IDIM 4096

__device__ int8_t g_Xq[(size_t)NTOK * IDIM];          // 16 MB
__device__ int8_t g_Wq[(size_t)ODIM * IDIM];          // 16 MB
__device__ float  g_corr[(size_t)ODIM * IDIM];        // 64 MB
__device__ float  g_sx[NTOK];
__device__ float  g_sw[ODIM];

// ---------------------------------------------------------------------------
__device__ __forceinline__ uint32_t smem_u32(const void* p) {
    uint32_t a;
    asm("{ .reg .u64 t; cvta.to.shared.u64 t, %1; cvt.u32.u64 %0, t; }"
        : "=r"(a) : "l"(p));
    return a;
}

__device__ __forceinline__ void cp_async16(uint32_t dst, const void* src) {
    asm volatile("cp.async.cg.shared.global [%0], [%1], 16;"
                 :: "r"(dst), "l"(src) : "memory");
}

__device__ __forceinline__ void ldsm4(uint32_t* r, uint32_t addr) {
    asm volatile("ldmatrix.sync.aligned.m8n8.x4.shared.b16 {%0,%1,%2,%3}, [%4];"
                 : "=r"(r[0]), "=r"(r[1]), "=r"(r[2]), "=r"(r[3]) : "r"(addr));
}

__device__ __forceinline__ void mma_s8(int* c, const uint32_t* a, const uint32_t* b) {
    asm volatile(
        "mma.sync.aligned.m16n8k32.row.col.s32.s8.s8.s32 "
        "{%0,%1,%2,%3}, {%4,%5,%6,%7}, {%8,%9}, {%0,%1,%2,%3};"
        : "+r"(c[0]), "+r"(c[1]), "+r"(c[2]), "+r"(c[3])
        : "r"(a[0]), "r"(a[1]), "r"(a[2]), "r"(a[3]), "r"(b[0]), "r"(b[1]));
}

// ---------------------------------------------------------------------------
// Kernel 1: per-token activation quant.  x[n,:] -> g_Xq (int8), g_sx[n]
// ---------------------------------------------------------------------------
__global__ void __launch_bounds__(256) k_quant_x(const float* __restrict__ x) {
    const int n = blockIdx.x, t = threadIdx.x;
    const float4* xr = (const float4*)(x + (size_t)n * IDIM) + t * 4;
    float v[16];
    float4 a0 = xr[0], a1 = xr[1], a2 = xr[2], a3 = xr[3];
    v[0]=a0.x; v[1]=a0.y; v[2]=a0.z; v[3]=a0.w;
    v[4]=a1.x; v[5]=a1.y; v[6]=a1.z; v[7]=a1.w;
    v[8]=a2.x; v[9]=a2.y; v[10]=a2.z; v[11]=a2.w;
    v[12]=a3.x; v[13]=a3.y; v[14]=a3.z; v[15]=a3.w;

    float m = 0.f;
    #pragma unroll
    for (int k = 0; k < 16; k++) m = fmaxf(m, fabsf(v[k]));

    __shared__ float red[8];
    __shared__ float s_inv;
    #pragma unroll
    for (int off = 16; off; off >>= 1) m = fmaxf(m, __shfl_xor_sync(0xFFFFFFFFu, m, off));
    if ((t & 31) == 0) red[t >> 5] = m;
    __syncthreads();
    if (t == 0) {
        float mm = red[0];
        #pragma unroll
        for (int k = 1; k < 8; k++) mm = fmaxf(mm, red[k]);
        float sv = mm / 127.0f;
        g_sx[n] = sv;
        s_inv = 1.0f / sv;     // one IEEE division per row
    }
    __syncthreads();
    float inv = s_inv;

    alignas(16) int8_t q[16];
    #pragma unroll
    for (int k = 0; k < 16; k++) {
        float r = rintf(v[k] * inv);               // round half to even == jnp.round
        r = fminf(fmaxf(r, -128.f), 127.f);
        q[k] = (int8_t)(int)r;
    }
    *(int4*)(g_Xq + (size_t)n * IDIM + t * 16) = *(const int4*)q;
}

// ---------------------------------------------------------------------------
// Kernel 2: corr = svd_up[O,32] @ svd_down[32,I]  (fp32), 64x64 tiles
// ---------------------------------------------------------------------------
__global__ void __launch_bounds__(256) k_corr(const float* __restrict__ up,
                                              const float* __restrict__ down) {
    __shared__ float su[64][33];
    __shared__ float sd[32][65];
    const int i0 = blockIdx.x * 64, o0 = blockIdx.y * 64;
    const int t = threadIdx.x;

    for (int j = t; j < 64 * 32; j += 256)
        su[j >> 5][j & 31] = up[(size_t)(o0 + (j >> 5)) * 32 + (j & 31)];
    for (int j = t; j < 32 * 64; j += 256)
        sd[j >> 6][j & 63] = down[(size_t)(j >> 6) * IDIM + i0 + (j & 63)];
    __syncthreads();

    const int ti = (t & 15) * 4, to = (t >> 4) * 4;
    float acc[4][4] = {};
    #pragma unroll
    for (int r = 0; r < 32; r++) {
        float ua[4], db[4];
        #pragma unroll
        for (int a = 0; a < 4; a++) ua[a] = su[to + a][r];
        #pragma unroll
        for (int b = 0; b < 4; b++) db[b] = sd[r][ti + b];
        #pragma unroll
        for (int a = 0; a < 4; a++)
            #pragma unroll
            for (int b = 0; b < 4; b++) acc[a][b] += ua[a] * db[b];
    }
    #pragma unroll
    for (int a = 0; a < 4; a++) {
        float4 v = make_float4(acc[a][0], acc[a][1], acc[a][2], acc[a][3]);
        *(float4*)(g_corr + (size_t)(o0 + to + a) * IDIM + i0 + ti) = v;
    }
}

// ---------------------------------------------------------------------------
// Kernel 3: dequant W row, row max -> g_sw[o], quant -> g_Wq (int8)
//   W[o,i] = (nibble - zp[o,g]) * scale[o,g] + corr[o,i],  g = i/64
// ---------------------------------------------------------------------------
__global__ void __launch_bounds__(256) k_quant_w(const int* __restrict__ wp,
                                                 const float* __restrict__ scale,
                                                 const float* __restrict__ zp) {
    const int o = blockIdx.x, t = threadIdx.x;
    const int4* pr = (const int4*)(wp + (size_t)o * 2048);
    int4 p0 = pr[2 * t], p1 = pr[2 * t + 1];
    int bv[8] = {p0.x, p0.y, p0.z, p0.w, p1.x, p1.y, p1.z, p1.w};

    const int g = t >> 2;               // 16 elems/thread, all in group i/64 = t/4
    const float z  = zp[o * 64 + g];
    const float sc = scale[o * 64 + g];

    const float4* cr = (const float4*)(g_corr + (size_t)o * IDIM + t * 16);
    float4 c0 = cr[0], c1 = cr[1], c2 = cr[2], c3 = cr[3];
    float cv[16] = {c0.x, c0.y, c0.z, c0.w, c1.x, c1.y, c1.z, c1.w,
                    c2.x, c2.y, c2.z, c2.w, c3.x, c3.y, c3.z, c3.w};

    float w[16];
    float m = 0.f;
    #pragma unroll
    for (int j = 0; j < 8; j++) {
        float qlo = (float)(bv[j] & 0xF);
        float qhi = (float)((bv[j] >> 4) & 0xF);
        w[2 * j]     = (qlo - z) * sc + cv[2 * j];
        w[2 * j + 1] = (qhi - z) * sc + cv[2 * j + 1];
        m = fmaxf(m, fmaxf(fabsf(w[2 * j]), fabsf(w[2 * j + 1])));
    }

    __shared__ float red[8];
    __shared__ float s_inv;
    #pragma unroll
    for (int off = 16; off; off >>= 1) m = fmaxf(m, __shfl_xor_sync(0xFFFFFFFFu, m, off));
    if ((t & 31) == 0) red[t >> 5] = m;
    __syncthreads();
    if (t == 0) {
        float mm = red[0];
        #pragma unroll
        for (int k = 1; k < 8; k++) mm = fmaxf(mm, red[k]);
        float sv = mm / 127.0f;
        g_sw[o] = sv;
        s_inv = 1.0f / sv;
    }
    __syncthreads();
    float inv = s_inv;

    alignas(16) int8_t q[16];
    #pragma unroll
    for (int k = 0; k < 16; k++) {
        float r = rintf(w[k] * inv);
        r = fminf(fmaxf(r, -128.f), 127.f);
        q[k] = (int8_t)(int)r;
    }
    *(int4*)(g_Wq + (size_t)o * IDIM + t * 16) = *(const int4*)q;
}

// ---------------------------------------------------------------------------
// Kernel 4: int8 IMMA GEMM, CTA 128x128, BK=64, 4-stage cp.async pipeline.
//   8 warps = 2(m) x 4(n); warp tile 64x32 -> 4 m16 x 4 n8 mma tiles, 2 k32
//   steps per BK. SMEM swizzle: 16B chunk c at row r -> c ^ ((r>>1)&3).
//   acc is bit-exact vs reference int32 GEMM; epilogue cvt.rn matches astype.
// ---------------------------------------------------------------------------
#define STAGES 4
#define GEMM_SMEM (STAGES * 16384)     // A 8KB + B 8KB per stage = 64 KB

__global__ void __launch_bounds__(256) k_gemm(const float* __restrict__ bias,
                                              float* __restrict__ out) {
    extern __shared__ int8_t smem[];
    const uint32_t sb = smem_u32(smem);
    const int t = threadIdx.x, lane = t & 31, wid = t >> 5;
    const int wm = wid >> 2, wn = wid & 3;        // 2 x 4 warp grid
    const int m0 = blockIdx.y * 128, o0 = blockIdx.x * 128;

    const int8_t* gA = g_Xq + (size_t)m0 * IDIM;
    const int8_t* gB = g_Wq + (size_t)o0 * IDIM;

    // ---- per-thread cp.async coordinates (2 x 16B chunks per matrix) ----
    uint32_t dstOff[2];
    uint32_t srcOff[2];
    #pragma unroll
    for (int q = 0; q < 2; q++) {
        int idx = t + q * 256;
        int r = idx >> 2, c = idx & 3;
        dstOff[q] = r * 64 + ((c ^ ((r >> 1) & 3)) << 4);
        srcOff[q] = r * IDIM + c * 16;
    }

    auto load_stage = [&](int kt, int s) {
        const uint32_t aB = sb + (uint32_t)s * 8192;
        const uint32_t bB = sb + STAGES * 8192 + (uint32_t)s * 8192;
        const uint32_t kb = (uint32_t)kt * 64;
        #pragma unroll
        for (int q = 0; q < 2; q++)
            cp_async16(aB + dstOff[q], gA + srcOff[q] + kb);
        #pragma unroll
        for (int q = 0; q < 2; q++)
            cp_async16(bB + dstOff[q], gB + srcOff[q] + kb);
        asm volatile("cp.async.commit_group;" ::: "memory");
    };

    // ---- ldmatrix lane addresses (stage-relative) ----
    uint32_t adA[4][2], adB[2][2];
    {
        const int lrA = lane & 15;
        const int hiA = (lane >> 4) & 1;          // byte-half within 32B k-step
        #pragma unroll
        for (int mi = 0; mi < 4; mi++) {
            int row = wm * 64 + mi * 16 + lrA;
            #pragma unroll
            for (int ks = 0; ks < 2; ks++) {
                int c = ks * 2 + hiA;
                adA[mi][ks] = row * 64 + ((c ^ ((row >> 1) & 3)) << 4);
            }
        }
        const int nb = wn * 32 + ((lane >> 4) & 1) * 8 + (lane & 7);
        const int hiB = (lane >> 3) & 1;
        #pragma unroll
        for (int p = 0; p < 2; p++) {
            int n = nb + p * 16;
            #pragma unroll
            for (int ks = 0; ks < 2; ks++) {
                int c = ks * 2 + hiB;
                adB[p][ks] = STAGES * 8192 + n * 64 + ((c ^ ((n >> 1) & 3)) << 4);
            }
        }
    }

    int acc[4][4][4] = {};

    // ---- prologue: prime 3 stages ----
    load_stage(0, 0);
    load_stage(1, 1);
    load_stage(2, 2);

    #pragma unroll 1
    for (int kt = 0; kt < 64; kt++) {
        const int s = kt & 3;
        if (kt <= 61)      asm volatile("cp.async.wait_group 2;" ::: "memory");
        else if (kt == 62) asm volatile("cp.async.wait_group 1;" ::: "memory");
        else               asm volatile("cp.async.wait_group 0;" ::: "memory");
        __syncthreads();

        if (kt + 3 < 64) load_stage(kt + 3, (kt + 3) & 3);

        const uint32_t sOff = sb + (uint32_t)s * 8192;
        #pragma unroll
        for (int ks = 0; ks < 2; ks++) {
            uint32_t a[4][4], b[2][4];
            #pragma unroll
            for (int mi = 0; mi < 4; mi++) ldsm4(a[mi], sOff + adA[mi][ks]);
            #pragma unroll
            for (int p = 0; p < 2; p++)    ldsm4(b[p],  sOff + adB[p][ks]);
            #pragma unroll
            for (int mi = 0; mi < 4; mi++)
                #pragma unroll
                for (int ni = 0; ni < 4; ni++)
                    mma_s8(acc[mi][ni], a[mi], &b[ni >> 1][(ni & 1) * 2]);
        }
    }

    // ---- fused epilogue: out = float(acc) * sx[row] * sw[col] + bias[col] ----
    const int r0 = lane >> 2;
    const int cq = (lane & 3) * 2;
    float swv[4][2], bvv[4][2];
    #pragma unroll
    for (int ni = 0; ni < 4; ni++) {
        int co = o0 + wn * 32 + ni * 8 + cq;
        swv[ni][0] = g_sw[co];     swv[ni][1] = g_sw[co + 1];
        bvv[ni][0] = bias[co];     bvv[ni][1] = bias[co + 1];
    }
    #pragma unroll
    for (int mi = 0; mi < 4; mi++) {
        #pragma unroll
        for (int h = 0; h < 2; h++) {
            int row = m0 + wm * 64 + mi * 16 + r0 + 8 * h;
            float sx = g_sx[row];
            float* op = out + (size_t)row * ODIM + o0 + wn * 32 + cq;
            #pragma unroll
            for (int ni = 0; ni < 4; ni++) {
                float2 v;
                v.x = (float)acc[mi][ni][2 * h]     * sx * swv[ni][0] + bvv[ni][0];
                v.y = (float)acc[mi][ni][2 * h + 1] * sx * swv[ni][1] + bvv[ni][1];
                *(float2*)(op + ni * 8) = v;
            }
        }
    }
}

// ---------------------------------------------------------------------------
extern "C" void kernel_launch(void* const* d_in, const int* in_sizes, int n_in,
                              void* d_out, int out_size) {
    const float* x     = (const float*)d_in[0];
    const int*   wp    = (const int*)  d_in[1];
    const float* up    = (const float*)d_in[2];
    const float* down  = (const float*)d_in[3];
    const float* scale = (const float*)d_in[4];
    const float* zp    = (const float*)d_in[5];
    const float* bias  = (const float*)d_in[6];
    float* out = (float*)d_out;

    k_quant_x<<<NTOK, 256>>>(x);
    k_corr<<<dim3(IDIM / 64, ODIM / 64), 256>>>(up, down);
    k_quant_w<<<ODIM, 256>>>(wp, scale, zp);

    static int smem_set = 0;
    if (!smem_set) {
        cudaFuncSetAttribute(k_gemm, cudaFuncAttributeMaxDynamicSharedMemorySize,
                             GEMM_SMEM);
        smem_set = 1;
    }
    k_gemm<<<dim3(ODIM / 128, NTOK / 128), 256, GEMM_SMEM>>>(bias, out);
}

// round 8
// speedup vs baseline: 1.2190x; 1.2190x over previous
#include <cuda_runtime.h>
#include <cuda_bf16.h>
#include <cstdint>
#include <cstddef>

// ============================================================================
// HQQSVDLinear forward_int8 on GB300 (sm_103 base ISA; tcgen05 blocked by
// toolchain — verified R6). R7 measured: legacy mma.sync pipe saturates at
// ~260 MACs/cyc/SM. R8: hybrid GEMM — 4 tensor warps (cols 0..63, mma.sync)
// + 4 dp4a warps (cols 64..127, fma/alu pipe) run concurrently per SM.
// Both paths are int32-exact vs the reference GEMM.
// ============================================================================

#define NTOK 4096
#define ODIM 4096
#define IDIM 4096

__device__ int8_t g_Xq[(size_t)NTOK * IDIM];          // 16 MB
__device__ int8_t g_Wq[(size_t)ODIM * IDIM];          // 16 MB
__device__ float  g_corr[(size_t)ODIM * IDIM];        // 64 MB
__device__ float  g_sx[NTOK];
__device__ float  g_sw[ODIM];

// ---------------------------------------------------------------------------
__device__ __forceinline__ uint32_t smem_u32(const void* p) {
    uint32_t a;
    asm("{ .reg .u64 t; cvta.to.shared.u64 t, %1; cvt.u32.u64 %0, t; }"
        : "=r"(a) : "l"(p));
    return a;
}

__device__ __forceinline__ void cp_async16(uint32_t dst, const void* src) {
    asm volatile("cp.async.cg.shared.global [%0], [%1], 16;"
                 :: "r"(dst), "l"(src) : "memory");
}

__device__ __forceinline__ void ldsm4(uint32_t* r, uint32_t addr) {
    asm volatile("ldmatrix.sync.aligned.m8n8.x4.shared.b16 {%0,%1,%2,%3}, [%4];"
                 : "=r"(r[0]), "=r"(r[1]), "=r"(r[2]), "=r"(r[3]) : "r"(addr));
}

__device__ __forceinline__ void lds128(uint32_t* r, uint32_t addr) {
    asm volatile("ld.shared.v4.b32 {%0,%1,%2,%3}, [%4];"
                 : "=r"(r[0]), "=r"(r[1]), "=r"(r[2]), "=r"(r[3]) : "r"(addr));
}

__device__ __forceinline__ void mma_s8(int* c, const uint32_t* a, const uint32_t* b) {
    asm volatile(
        "mma.sync.aligned.m16n8k32.row.col.s32.s8.s8.s32 "
        "{%0,%1,%2,%3}, {%4,%5,%6,%7}, {%8,%9}, {%0,%1,%2,%3};"
        : "+r"(c[0]), "+r"(c[1]), "+r"(c[2]), "+r"(c[3])
        : "r"(a[0]), "r"(a[1]), "r"(a[2]), "r"(a[3]), "r"(b[0]), "r"(b[1]));
}

// ---------------------------------------------------------------------------
// Kernel 1: per-token activation quant.  x[n,:] -> g_Xq (int8), g_sx[n]
// ---------------------------------------------------------------------------
__global__ void __launch_bounds__(256) k_quant_x(const float* __restrict__ x) {
    const int n = blockIdx.x, t = threadIdx.x;
    const float4* xr = (const float4*)(x + (size_t)n * IDIM) + t * 4;
    float v[16];
    float4 a0 = xr[0], a1 = xr[1], a2 = xr[2], a3 = xr[3];
    v[0]=a0.x; v[1]=a0.y; v[2]=a0.z; v[3]=a0.w;
    v[4]=a1.x; v[5]=a1.y; v[6]=a1.z; v[7]=a1.w;
    v[8]=a2.x; v[9]=a2.y; v[10]=a2.z; v[11]=a2.w;
    v[12]=a3.x; v[13]=a3.y; v[14]=a3.z; v[15]=a3.w;

    float m = 0.f;
    #pragma unroll
    for (int k = 0; k < 16; k++) m = fmaxf(m, fabsf(v[k]));

    __shared__ float red[8];
    __shared__ float s_inv;
    #pragma unroll
    for (int off = 16; off; off >>= 1) m = fmaxf(m, __shfl_xor_sync(0xFFFFFFFFu, m, off));
    if ((t & 31) == 0) red[t >> 5] = m;
    __syncthreads();
    if (t == 0) {
        float mm = red[0];
        #pragma unroll
        for (int k = 1; k < 8; k++) mm = fmaxf(mm, red[k]);
        float sv = mm / 127.0f;
        g_sx[n] = sv;
        s_inv = 1.0f / sv;
    }
    __syncthreads();
    float inv = s_inv;

    alignas(16) int8_t q[16];
    #pragma unroll
    for (int k = 0; k < 16; k++) {
        float r = rintf(v[k] * inv);
        r = fminf(fmaxf(r, -128.f), 127.f);
        q[k] = (int8_t)(int)r;
    }
    *(int4*)(g_Xq + (size_t)n * IDIM + t * 16) = *(const int4*)q;
}

// ---------------------------------------------------------------------------
// Kernel 2: corr = svd_up[O,32] @ svd_down[32,I]  (fp32), 64x64 tiles
// ---------------------------------------------------------------------------
__global__ void __launch_bounds__(256) k_corr(const float* __restrict__ up,
                                              const float* __restrict__ down) {
    __shared__ float su[64][33];
    __shared__ float sd[32][65];
    const int i0 = blockIdx.x * 64, o0 = blockIdx.y * 64;
    const int t = threadIdx.x;

    for (int j = t; j < 64 * 32; j += 256)
        su[j >> 5][j & 31] = up[(size_t)(o0 + (j >> 5)) * 32 + (j & 31)];
    for (int j = t; j < 32 * 64; j += 256)
        sd[j >> 6][j & 63] = down[(size_t)(j >> 6) * IDIM + i0 + (j & 63)];
    __syncthreads();

    const int ti = (t & 15) * 4, to = (t >> 4) * 4;
    float acc[4][4] = {};
    #pragma unroll
    for (int r = 0; r < 32; r++) {
        float ua[4], db[4];
        #pragma unroll
        for (int a = 0; a < 4; a++) ua[a] = su[to + a][r];
        #pragma unroll
        for (int b = 0; b < 4; b++) db[b] = sd[r][ti + b];
        #pragma unroll
        for (int a = 0; a < 4; a++)
            #pragma unroll
            for (int b = 0; b < 4; b++) acc[a][b] += ua[a] * db[b];
    }
    #pragma unroll
    for (int a = 0; a < 4; a++) {
        float4 v = make_float4(acc[a][0], acc[a][1], acc[a][2], acc[a][3]);
        *(float4*)(g_corr + (size_t)(o0 + to + a) * IDIM + i0 + ti) = v;
    }
}

// ---------------------------------------------------------------------------
// Kernel 3: dequant W row, row max -> g_sw[o], quant -> g_Wq (int8)
// ---------------------------------------------------------------------------
__global__ void __launch_bounds__(256) k_quant_w(const int* __restrict__ wp,
                                                 const float* __restrict__ scale,
                                                 const float* __restrict__ zp) {
    const int o = blockIdx.x, t = threadIdx.x;
    const int4* pr = (const int4*)(wp + (size_t)o * 2048);
    int4 p0 = pr[2 * t], p1 = pr[2 * t + 1];
    int bv[8] = {p0.x, p0.y, p0.z, p0.w, p1.x, p1.y, p1.z, p1.w};

    const int g = t >> 2;
    const float z  = zp[o * 64 + g];
    const float sc = scale[o * 64 + g];

    const float4* cr = (const float4*)(g_corr + (size_t)o * IDIM + t * 16);
    float4 c0 = cr[0], c1 = cr[1], c2 = cr[2], c3 = cr[3];
    float cv[16] = {c0.x, c0.y, c0.z, c0.w, c1.x, c1.y, c1.z, c1.w,
                    c2.x, c2.y, c2.z, c2.w, c3.x, c3.y, c3.z, c3.w};

    float w[16];
    float m = 0.f;
    #pragma unroll
    for (int j = 0; j < 8; j++) {
        float qlo = (float)(bv[j] & 0xF);
        float qhi = (float)((bv[j] >> 4) & 0xF);
        w[2 * j]     = (qlo - z) * sc + cv[2 * j];
        w[2 * j + 1] = (qhi - z) * sc + cv[2 * j + 1];
        m = fmaxf(m, fmaxf(fabsf(w[2 * j]), fabsf(w[2 * j + 1])));
    }

    __shared__ float red[8];
    __shared__ float s_inv;
    #pragma unroll
    for (int off = 16; off; off >>= 1) m = fmaxf(m, __shfl_xor_sync(0xFFFFFFFFu, m, off));
    if ((t & 31) == 0) red[t >> 5] = m;
    __syncthreads();
    if (t == 0) {
        float mm = red[0];
        #pragma unroll
        for (int k = 1; k < 8; k++) mm = fmaxf(mm, red[k]);
        float sv = mm / 127.0f;
        g_sw[o] = sv;
        s_inv = 1.0f / sv;
    }
    __syncthreads();
    float inv = s_inv;

    alignas(16) int8_t q[16];
    #pragma unroll
    for (int k = 0; k < 16; k++) {
        float r = rintf(w[k] * inv);
        r = fminf(fmaxf(r, -128.f), 127.f);
        q[k] = (int8_t)(int)r;
    }
    *(int4*)(g_Wq + (size_t)o * IDIM + t * 16) = *(const int4*)q;
}

// ---------------------------------------------------------------------------
// Kernel 4: hybrid int8 GEMM, CTA 128x128, BK=64, 4-stage cp.async pipeline.
//   Warps 0-3 (one per SMSP): mma.sync m16n8k32, cols 0..63  (2x2 warp grid,
//     warp tile 64x32).
//   Warps 4-7 (one per SMSP): dp4a, cols 64..127. Warp w-4 covers rows
//     (w-4)*32..+32. Lane: 4 consecutive rows ((lane>>2)*4), 16 cols
//     ((lane&3)*16). Chunk-rotation cg^=lane&3 on both A and B reads breaks
//     the stride-16-row bank aliasing.
//   Both paths accumulate exact int32; fused float epilogue.
// ---------------------------------------------------------------------------
#define STAGES 4
#define GEMM_SMEM (STAGES * 16384)     // A 8KB + B 8KB per stage = 64 KB

__global__ void __launch_bounds__(256) k_gemm(const float* __restrict__ bias,
                                              float* __restrict__ out) {
    extern __shared__ int8_t smem[];
    const uint32_t sb = smem_u32(smem);
    const int t = threadIdx.x, lane = t & 31, wid = t >> 5;
    const int m0 = blockIdx.y * 128, o0 = blockIdx.x * 128;

    const int8_t* gA = g_Xq + (size_t)m0 * IDIM;
    const int8_t* gB = g_Wq + (size_t)o0 * IDIM;

    // ---- per-thread cp.async coordinates (2 x 16B chunks per matrix) ----
    uint32_t dstOff[2], srcOff[2];
    #pragma unroll
    for (int q = 0; q < 2; q++) {
        int idx = t + q * 256;
        int r = idx >> 2, c = idx & 3;
        dstOff[q] = r * 64 + ((c ^ ((r >> 1) & 3)) << 4);
        srcOff[q] = r * IDIM + c * 16;
    }

    auto load_stage = [&](int kt, int s) {
        const uint32_t aB = sb + (uint32_t)s * 8192;
        const uint32_t bB = sb + STAGES * 8192 + (uint32_t)s * 8192;
        const uint32_t kb = (uint32_t)kt * 64;
        #pragma unroll
        for (int q = 0; q < 2; q++)
            cp_async16(aB + dstOff[q], gA + srcOff[q] + kb);
        #pragma unroll
        for (int q = 0; q < 2; q++)
            cp_async16(bB + dstOff[q], gB + srcOff[q] + kb);
        asm volatile("cp.async.commit_group;" ::: "memory");
    };

    // =========== tensor-warp state (wid 0..3): 2(m) x 2(n) grid ===========
    const int wm = (wid >> 1) & 1, wn = wid & 1;
    uint32_t adA[4][2], adB[2][2];
    int accT[4][4][4] = {};
    if (wid < 4) {
        const int lrA = lane & 15;
        const int hiA = (lane >> 4) & 1;
        #pragma unroll
        for (int mi = 0; mi < 4; mi++) {
            int row = wm * 64 + mi * 16 + lrA;
            #pragma unroll
            for (int ks = 0; ks < 2; ks++) {
                int c = ks * 2 + hiA;
                adA[mi][ks] = row * 64 + ((c ^ ((row >> 1) & 3)) << 4);
            }
        }
        const int nb = wn * 32 + ((lane >> 4) & 1) * 8 + (lane & 7);
        const int hiB = (lane >> 3) & 1;
        #pragma unroll
        for (int p = 0; p < 2; p++) {
            int n = nb + p * 16;
            #pragma unroll
            for (int ks = 0; ks < 2; ks++) {
                int c = ks * 2 + hiB;
                adB[p][ks] = STAGES * 8192 + n * 64 + ((c ^ ((n >> 1) & 3)) << 4);
            }
        }
    }

    // =========== dp4a-warp state (wid 4..7) ===========
    const int wd = wid - 4;
    const int rbase = wd * 32 + ((lane >> 2) << 2);   // 4 consecutive rows
    const int c4 = lane & 3;                          // column group
    uint32_t aRow[4], xA[4];
    int accD[4][16] = {};
    const uint32_t bBaseLane = STAGES * 8192 + 4096 + (uint32_t)c4 * 1024;
    if (wid >= 4) {
        #pragma unroll
        for (int ri = 0; ri < 4; ri++) {
            int r = rbase + ri;
            aRow[ri] = (uint32_t)r * 64;
            xA[ri] = (uint32_t)((r >> 1) & 3);
        }
    }

    // ---- prologue: prime 3 stages ----
    load_stage(0, 0);
    load_stage(1, 1);
    load_stage(2, 2);

    #pragma unroll 1
    for (int kt = 0; kt < 64; kt++) {
        const int s = kt & 3;
        if (kt <= 61)      asm volatile("cp.async.wait_group 2;" ::: "memory");
        else if (kt == 62) asm volatile("cp.async.wait_group 1;" ::: "memory");
        else               asm volatile("cp.async.wait_group 0;" ::: "memory");
        __syncthreads();

        if (kt + 3 < 64) load_stage(kt + 3, (kt + 3) & 3);

        const uint32_t sOff = sb + (uint32_t)s * 8192;

        if (wid < 4) {
            // ---------------- tensor path: cols 0..63 ----------------
            #pragma unroll
            for (int ks = 0; ks < 2; ks++) {
                uint32_t a[4][4], b[2][4];
                #pragma unroll
                for (int mi = 0; mi < 4; mi++) ldsm4(a[mi], sOff + adA[mi][ks]);
                #pragma unroll
                for (int p = 0; p < 2; p++)    ldsm4(b[p],  sOff + adB[p][ks]);
                #pragma unroll
                for (int mi = 0; mi < 4; mi++)
                    #pragma unroll
                    for (int ni = 0; ni < 4; ni++)
                        mma_s8(accT[mi][ni], a[mi], &b[ni >> 1][(ni & 1) * 2]);
            }
        } else {
            // ---------------- dp4a path: cols 64..127 ----------------
            #pragma unroll
            for (int cgi = 0; cgi < 4; cgi++) {
                const uint32_t cg = (uint32_t)((cgi + c4) & 3);
                uint32_t a[4][4];
                #pragma unroll
                for (int ri = 0; ri < 4; ri++)
                    lds128(a[ri], sOff + aRow[ri] + ((cg ^ xA[ri]) << 4));
                #pragma unroll
                for (int q = 0; q < 4; q++) {
                    uint32_t b[4][4];
                    #pragma unroll
                    for (int j = 0; j < 4; j++) {
                        const int cj = q * 4 + j;
                        const uint32_t xB = (uint32_t)((cj >> 1) & 3);
                        lds128(b[j], sOff + bBaseLane + (uint32_t)cj * 64 +
                                     ((cg ^ xB) << 4));
                    }
                    #pragma unroll
                    for (int j = 0; j < 4; j++)
                        #pragma unroll
                        for (int kk = 0; kk < 4; kk++)
                            #pragma unroll
                            for (int ri = 0; ri < 4; ri++)
                                accD[ri][q * 4 + j] =
                                    __dp4a((int)a[ri][kk], (int)b[j][kk],
                                           accD[ri][q * 4 + j]);
                }
            }
        }
    }

    // ---- fused epilogue: out = float(acc) * sx[row] * sw[col] + bias[col] ----
    if (wid < 4) {
        const int r0 = lane >> 2;
        const int cq = (lane & 3) * 2;
        float swv[4][2], bvv[4][2];
        #pragma unroll
        for (int ni = 0; ni < 4; ni++) {
            int co = o0 + wn * 32 + ni * 8 + cq;
            swv[ni][0] = g_sw[co];     swv[ni][1] = g_sw[co + 1];
            bvv[ni][0] = bias[co];     bvv[ni][1] = bias[co + 1];
        }
        #pragma unroll
        for (int mi = 0; mi < 4; mi++) {
            #pragma unroll
            for (int h = 0; h < 2; h++) {
                int row = m0 + wm * 64 + mi * 16 + r0 + 8 * h;
                float sx = g_sx[row];
                float* op = out + (size_t)row * ODIM + o0 + wn * 32 + cq;
                #pragma unroll
                for (int ni = 0; ni < 4; ni++) {
                    float2 v;
                    v.x = (float)accT[mi][ni][2 * h]     * sx * swv[ni][0] + bvv[ni][0];
                    v.y = (float)accT[mi][ni][2 * h + 1] * sx * swv[ni][1] + bvv[ni][1];
                    *(float2*)(op + ni * 8) = v;
                }
            }
        }
    } else {
        const int cbase = o0 + 64 + c4 * 16;
        float swv[16], bvv[16];
        #pragma unroll
        for (int cj = 0; cj < 16; cj += 4) {
            *(float4*)&swv[cj] = *(const float4*)&g_sw[cbase + cj];
            *(float4*)&bvv[cj] = *(const float4*)&bias[cbase + cj];
        }
        #pragma unroll
        for (int ri = 0; ri < 4; ri++) {
            int row = m0 + rbase + ri;
            float sx = g_sx[row];
            float* op = out + (size_t)row * ODIM + cbase;
            #pragma unroll
            for (int cj = 0; cj < 16; cj += 4) {
                float4 v;
                v.x = (float)accD[ri][cj]     * sx * swv[cj]     + bvv[cj];
                v.y = (float)accD[ri][cj + 1] * sx * swv[cj + 1] + bvv[cj + 1];
                v.z = (float)accD[ri][cj + 2] * sx * swv[cj + 2] + bvv[cj + 2];
                v.w = (float)accD[ri][cj + 3] * sx * swv[cj + 3] + bvv[cj + 3];
                *(float4*)(op + cj) = v;
            }
        }
    }
}

// ---------------------------------------------------------------------------
extern "C" void kernel_launch(void* const* d_in, const int* in_sizes, int n_in,
                              void* d_out, int out_size) {
    const float* x     = (const float*)d_in[0];
    const int*   wp    = (const int*)  d_in[1];
    const float* up    = (const float*)d_in[2];
    const float* down  = (const float*)d_in[3];
    const float* scale = (const float*)d_in[4];
    const float* zp    = (const float*)d_in[5];
    const float* bias  = (const float*)d_in[6];
    float* out = (float*)d_out;

    k_quant_x<<<NTOK, 256>>>(x);
    k_corr<<<dim3(IDIM / 64, ODIM / 64), 256>>>(up, down);
    k_quant_w<<<ODIM, 256>>>(wp, scale, zp);

    static int smem_set = 0;
    if (!smem_set) {
        cudaFuncSetAttribute(k_gemm, cudaFuncAttributeMaxDynamicSharedMemorySize,
                             GEMM_SMEM);
        smem_set = 1;
    }
    k_gemm<<<dim3(ODIM / 128, NTOK / 128), 256, GEMM_SMEM>>>(bias, out);
}